// round 10
// baseline (speedup 1.0000x reference)
#include <cuda_runtime.h>
#include <cuda_fp16.h>
#include <math.h>
#include <stdint.h>

#define N_TOK 4096
#define D_MOD 512

// scratch (static device globals — no allocation allowed)
__device__ __half g_Xh[N_TOK * D_MOD];
__device__ __half g_Wqh[D_MOD * D_MOD];
__device__ __half g_Wkh[D_MOD * D_MOD];
__device__ __half g_Wvh[D_MOD * D_MOD];
__device__ __half g_Qh[N_TOK * D_MOD];
__device__ __half g_Kh[N_TOK * D_MOD];
__device__ __half g_Vh[N_TOK * D_MOD];
__device__ __half g_Vth[D_MOD * N_TOK];         // V^T [512][4096]
__device__ __half g_Sh[(size_t)N_TOK * N_TOK];  // exp(scores), unnormalized
__device__ float  g_sigma[N_TOK];               // accumulated x.Ws (clamp at use)
__device__ float  g_rowsum[N_TOK];              // sum of exp per row

__device__ __forceinline__ uint32_t smem_u32(const void* p) {
    uint32_t a;
    asm("{ .reg .u64 t; cvta.to.shared.u64 t, %1; cvt.u32.u64 %0, t; }" : "=r"(a) : "l"(p));
    return a;
}
__device__ __forceinline__ void mma_f16(float* d, const uint32_t* a, const uint32_t* b) {
    asm volatile(
        "mma.sync.aligned.m16n8k16.row.col.f32.f16.f16.f32 "
        "{%0,%1,%2,%3}, {%4,%5,%6,%7}, {%8,%9}, {%0,%1,%2,%3};"
        : "+f"(d[0]), "+f"(d[1]), "+f"(d[2]), "+f"(d[3])
        : "r"(a[0]), "r"(a[1]), "r"(a[2]), "r"(a[3]), "r"(b[0]), "r"(b[1]));
}
__device__ __forceinline__ void ldsm4(uint32_t* r, uint32_t addr) {
    asm volatile("ldmatrix.sync.aligned.m8n8.x4.shared.b16 {%0,%1,%2,%3}, [%4];"
        : "=r"(r[0]), "=r"(r[1]), "=r"(r[2]), "=r"(r[3]) : "r"(addr));
}
__device__ __forceinline__ void cp16(uint32_t s, const void* g) {
    asm volatile("cp.async.cg.shared.global [%0], [%1], 16;" :: "r"(s), "l"(g));
}

// ---------------------------------------------------------------------------
// cp.async 3-stage fp16 GEMM (fp32 accumulate), ldmatrix fragment loads.
//   C[M,NC] = alpha * A[M,K] * B[NC,K]^T   (both K-major row-major fp16)
// Epilogue modes: 1 fp16 store | 2 exp->fp16 + rowsum atomics | 3 fp32/rowsum
// 96 KB smem -> 2 CTAs/SM.
// ---------------------------------------------------------------------------
#define STAGES 3
#define TILE_BYTES 16384
#define STAGE_BYTES (2 * TILE_BYTES)
#define DYN_SMEM (STAGES * STAGE_BYTES)       // 96 KB

template <int MODE>
__device__ __forceinline__ void gemm_fp16(
    const __half* __restrict__ A, const __half* __restrict__ B,
    void* __restrict__ Cv, int K, int NC, float alpha)
{
    extern __shared__ __half smh[];
    const uint32_t smem_base = smem_u32(smh);
    const int t    = threadIdx.x;
    const int wid  = t >> 5;
    const int lane = t & 31;
    const int r    = lane >> 2;
    const int c    = lane & 3;
    const int warpM = (wid >> 2) * 64;
    const int warpN = (wid & 3) * 32;
    const int row0 = blockIdx.y * 128;
    const int col0 = blockIdx.x * 128;
    const int iters = K >> 6;

    auto stage_load = [&](int sidx) {
        const int buf = sidx % STAGES;
        const int k0  = sidx << 6;
        const uint32_t abase = smem_base + (uint32_t)buf * STAGE_BYTES;
        const uint32_t bbase = abase + TILE_BYTES;
#pragma unroll
        for (int i = 0; i < 4; i++) {
            int lc = i * 256 + t;
            int rr = lc >> 3, cc = lc & 7;
            uint32_t so = (uint32_t)((rr << 3) + (cc ^ (rr & 7))) << 4;
            cp16(abase + so, &A[(size_t)(row0 + rr) * K + k0 + (cc << 3)]);
            cp16(bbase + so, &B[(size_t)(col0 + rr) * K + k0 + (cc << 3)]);
        }
        asm volatile("cp.async.commit_group;" ::: "memory");
    };

    const int a_row_lo = lane & 15;
    const int a_chi    = lane >> 4;
    const int b_row_lo = (lane & 7) + ((lane >> 4) << 3);
    const int b_chi    = (lane >> 3) & 1;

    float acc[4][4][4] = {};

    stage_load(0);
    stage_load(1);

    for (int it = 0; it < iters; ++it) {
        const int buf = it % STAGES;
        asm volatile("cp.async.wait_group %0;" :: "n"(STAGES - 2) : "memory");
        __syncthreads();
        if (it + STAGES - 1 < iters) stage_load(it + STAGES - 1);

        const uint32_t abase = smem_base + (uint32_t)buf * STAGE_BYTES;
        const uint32_t bbase = abase + TILE_BYTES;

#pragma unroll
        for (int kk4 = 0; kk4 < 4; kk4++) {
            const int ca = kk4 * 2 + a_chi;
            const int cb = kk4 * 2 + b_chi;
            uint32_t af[4][4], bq[2][4];
#pragma unroll
            for (int mi = 0; mi < 4; mi++) {
                int row = warpM + mi * 16 + a_row_lo;
                uint32_t addr = abase + ((uint32_t)((row << 3) + (ca ^ (row & 7))) << 4);
                ldsm4(af[mi], addr);
            }
#pragma unroll
            for (int np = 0; np < 2; np++) {
                int row = warpN + np * 16 + b_row_lo;
                uint32_t addr = bbase + ((uint32_t)((row << 3) + (cb ^ (row & 7))) << 4);
                ldsm4(bq[np], addr);
            }
#pragma unroll
            for (int mi = 0; mi < 4; mi++)
#pragma unroll
                for (int ni = 0; ni < 4; ni++)
                    mma_f16(acc[mi][ni], af[mi], &bq[ni >> 1][(ni & 1) * 2]);
        }
    }

    // ---- epilogue
#pragma unroll
    for (int mi = 0; mi < 4; mi++) {
        int row = row0 + warpM + mi * 16 + r;
        float rs0 = 0.f, rs1 = 0.f;
        float inv0 = 1.f, inv1 = 1.f;
        if (MODE == 3) {
            inv0 = 1.0f / g_rowsum[row];
            inv1 = 1.0f / g_rowsum[row + 8];
        }
#pragma unroll
        for (int ni = 0; ni < 4; ni++) {
            int col = col0 + warpN + ni * 8 + 2 * c;
            float o0 = alpha * acc[mi][ni][0], o1 = alpha * acc[mi][ni][1];
            float o2 = alpha * acc[mi][ni][2], o3 = alpha * acc[mi][ni][3];
            if (MODE == 1) {
                __half* Ch = (__half*)Cv;
                *(__half2*)&Ch[(size_t)row * NC + col]       = __floats2half2_rn(o0, o1);
                *(__half2*)&Ch[(size_t)(row + 8) * NC + col] = __floats2half2_rn(o2, o3);
            } else if (MODE == 2) {
                float e0 = fminf(__expf(o0), 60000.f);
                float e1 = fminf(__expf(o1), 60000.f);
                float e2 = fminf(__expf(o2), 60000.f);
                float e3 = fminf(__expf(o3), 60000.f);
                __half* Ch = (__half*)Cv;
                *(__half2*)&Ch[(size_t)row * NC + col]       = __floats2half2_rn(e0, e1);
                *(__half2*)&Ch[(size_t)(row + 8) * NC + col] = __floats2half2_rn(e2, e3);
                rs0 += e0 + e1;
                rs1 += e2 + e3;
            } else if (MODE == 3) {
                float* Cf = (float*)Cv;
                *(float2*)&Cf[(size_t)row * NC + col]       = make_float2(o0 * inv0, o1 * inv0);
                *(float2*)&Cf[(size_t)(row + 8) * NC + col] = make_float2(o2 * inv1, o3 * inv1);
            }
        }
        if (MODE == 2) {
            rs0 += __shfl_xor_sync(0xffffffffu, rs0, 1);
            rs0 += __shfl_xor_sync(0xffffffffu, rs0, 2);
            rs1 += __shfl_xor_sync(0xffffffffu, rs1, 1);
            rs1 += __shfl_xor_sync(0xffffffffu, rs1, 2);
            if (c == 0) {
                atomicAdd(&g_rowsum[row],     rs0);
                atomicAdd(&g_rowsum[row + 8], rs1);
            }
        }
    }
}

__global__ void __launch_bounds__(256, 2) qkv_h_kernel()
{
    if (blockIdx.z == 0)      gemm_fp16<1>(g_Xh, g_Wqh, g_Qh, D_MOD, D_MOD, 1.0f);
    else if (blockIdx.z == 1) gemm_fp16<1>(g_Xh, g_Wkh, g_Kh, D_MOD, D_MOD, 1.0f);
    else                      gemm_fp16<1>(g_Xh, g_Wvh, g_Vh, D_MOD, D_MOD, 1.0f);
}

__global__ void __launch_bounds__(256, 2) s_h_kernel()
{
    gemm_fp16<2>(g_Qh, g_Kh, g_Sh, D_MOD, N_TOK, 0.044194173824159216f); // 1/sqrt(512)
}

__global__ void __launch_bounds__(256, 2) z_h_kernel(float* __restrict__ Z)
{
    gemm_fp16<3>(g_Sh, g_Vth, Z, N_TOK, D_MOD, 1.0f);
}

// ---------------------------------------------------------------------------
// fused fp32 -> fp16 convert for x, Wq, Wk, Wv + sigma partial dot (x rows)
// ---------------------------------------------------------------------------
#define X4   (N_TOK * D_MOD / 4)
#define W4   (D_MOD * D_MOD / 4)

__global__ void cvt_all_kernel(const float4* __restrict__ x,
                               const float4* __restrict__ Wq,
                               const float4* __restrict__ Wk,
                               const float4* __restrict__ Wv,
                               const float4* __restrict__ Ws)
{
    int i = blockIdx.x * blockDim.x + threadIdx.x;
    if (i < X4) {
        float4 v = x[i];
        *(__half2*)&g_Xh[i * 4]     = __floats2half2_rn(v.x, v.y);
        *(__half2*)&g_Xh[i * 4 + 2] = __floats2half2_rn(v.z, v.w);
        float4 w = Ws[i & 127];
        float s = v.x * w.x + v.y * w.y + v.z * w.z + v.w * w.w;
#pragma unroll
        for (int o = 16; o; o >>= 1) s += __shfl_xor_sync(0xffffffffu, s, o);
        if ((threadIdx.x & 31) == 0) atomicAdd(&g_sigma[i >> 7], s);
        return;
    }
    const float4* in;
    __half* out;
    int idx;
    if (i < X4 + W4)           { in = Wq; out = g_Wqh; idx = i - X4; }
    else if (i < X4 + 2 * W4)  { in = Wk; out = g_Wkh; idx = i - X4 - W4; }
    else if (i < X4 + 3 * W4)  { in = Wv; out = g_Wvh; idx = i - X4 - 2 * W4; }
    else return;
    float4 v = in[idx];
    *(__half2*)&out[idx * 4]     = __floats2half2_rn(v.x, v.y);
    *(__half2*)&out[idx * 4 + 2] = __floats2half2_rn(v.z, v.w);
}

// ---------------------------------------------------------------------------
// transpose g_Vh [4096][512] -> g_Vth [512][4096]
// ---------------------------------------------------------------------------
__global__ void transpose_v_kernel()
{
    __shared__ __half tile[32][33];
    const int c0 = blockIdx.x * 32;
    const int r0 = blockIdx.y * 32;
    const int tx = threadIdx.x & 31;
    const int ty = threadIdx.x >> 5;
#pragma unroll
    for (int i = 0; i < 4; i++) {
        int row = ty + i * 8;
        tile[row][tx] = g_Vh[(size_t)(r0 + row) * D_MOD + c0 + tx];
    }
    __syncthreads();
#pragma unroll
    for (int i = 0; i < 4; i++) {
        int row = ty + i * 8;
        g_Vth[(size_t)(c0 + row) * N_TOK + r0 + tx] = tile[tx][row];
    }
}

// ---------------------------------------------------------------------------
// P row kernel: zero row + Gaussian band; clamps sigma at use.
// fp32 underflow: exp term is exactly 0 for |i-j| >= 15 since sigma <= 1.
// ---------------------------------------------------------------------------
#define BAND 32

__global__ void p_row_kernel(float* __restrict__ P)
{
    const int row = blockIdx.x;
    const int t = threadIdx.x;
    float4* prow4 = (float4*)(P + (size_t)row * N_TOK);
#pragma unroll
    for (int j = t; j < N_TOK / 4; j += 256)
        prow4[j] = make_float4(0.f, 0.f, 0.f, 0.f);
    __syncthreads();

    if (t < 32) {
        const int lane = t;
        const float sg  = fminf(fmaxf(g_sigma[row], 0.001f), 1.0f);
        const float inv = 1.0f / sg;
        const float cc  = rsqrtf(6.283185307179586f * sg);
        const int j0 = max(row - BAND, 0);
        const int j1 = min(row + BAND, N_TOK - 1);

        float sum = 0.f;
        for (int j = j0 + lane; j <= j1; j += 32) {
            float u = (float)(j - row) * inv;
            sum += cc * __expf(-0.5f * u * u);
        }
#pragma unroll
        for (int o = 16; o; o >>= 1) sum += __shfl_xor_sync(0xffffffffu, sum, o);
        const float scale = 1.0f / (sum + 1e-8f);

        for (int j = j0 + lane; j <= j1; j += 32) {
            float u = (float)(j - row) * inv;
            P[(size_t)row * N_TOK + j] = cc * __expf(-0.5f * u * u) * scale;
        }
    }
}

// ---------------------------------------------------------------------------
// scale S: S_fp32 = e_fp16 * (1/rowsum). 4 blocks per row, 4 floats/thread.
// ---------------------------------------------------------------------------
__global__ void scale_s_kernel(float* __restrict__ S)
{
    __shared__ float sh_inv;
    const int b = blockIdx.x;
    const int row = b >> 2;
    if (threadIdx.x == 0) sh_inv = 1.0f / g_rowsum[row];
    __syncthreads();
    const float inv = sh_inv;
    const size_t base = (size_t)b * 1024 + threadIdx.x * 4;
    __half2 h01 = *(const __half2*)&g_Sh[base];
    __half2 h23 = *(const __half2*)&g_Sh[base + 2];
    float2 f01 = __half22float2(h01);
    float2 f23 = __half22float2(h23);
    float4 o;
    o.x = f01.x * inv; o.y = f01.y * inv;
    o.z = f23.x * inv; o.w = f23.y * inv;
    *(float4*)&S[base] = o;
}

// ---------------------------------------------------------------------------
extern "C" void kernel_launch(void* const* d_in, const int* in_sizes, int n_in,
                              void* d_out, int out_size)
{
    const float* x  = (const float*)d_in[0];
    const float* Wq = (const float*)d_in[1];
    const float* Wk = (const float*)d_in[2];
    const float* Wv = (const float*)d_in[3];
    const float* Ws = (const float*)d_in[4];

    float* out = (float*)d_out;
    float* Z = out;                          // [4096, 512]
    float* P = out + (size_t)N_TOK * D_MOD;  // [4096, 4096]
    float* S = P + (size_t)N_TOK * N_TOK;    // [4096, 4096]

    static cudaStream_t sA = nullptr;
    static cudaEvent_t eCvt, eQKV, eS, eT, eSc;
    if (!sA) {
        cudaStreamCreateWithFlags(&sA, cudaStreamNonBlocking);
        cudaEventCreateWithFlags(&eCvt, cudaEventDisableTiming);
        cudaEventCreateWithFlags(&eQKV, cudaEventDisableTiming);
        cudaEventCreateWithFlags(&eS,   cudaEventDisableTiming);
        cudaEventCreateWithFlags(&eT,   cudaEventDisableTiming);
        cudaEventCreateWithFlags(&eSc,  cudaEventDisableTiming);
        cudaFuncSetAttribute(qkv_h_kernel, cudaFuncAttributeMaxDynamicSharedMemorySize, DYN_SMEM);
        cudaFuncSetAttribute(s_h_kernel,   cudaFuncAttributeMaxDynamicSharedMemorySize, DYN_SMEM);
        cudaFuncSetAttribute(z_h_kernel,   cudaFuncAttributeMaxDynamicSharedMemorySize, DYN_SMEM);
    }

    float *sigp, *rsp;
    cudaGetSymbolAddress((void**)&sigp, g_sigma);
    cudaGetSymbolAddress((void**)&rsp,  g_rowsum);

    dim3 blk(256);

    // main: zero accumulators, convert + sigma partials
    cudaMemsetAsync(sigp, 0, N_TOK * sizeof(float));
    cudaMemsetAsync(rsp,  0, N_TOK * sizeof(float));
    cvt_all_kernel<<<(X4 + 3 * W4) / 256, blk>>>(
        (const float4*)x, (const float4*)Wq, (const float4*)Wk,
        (const float4*)Wv, (const float4*)Ws);
    cudaEventRecord(eCvt, 0);

    // main: QKV GEMM
    dim3 gQKV(D_MOD / 128, N_TOK / 128, 3);
    qkv_h_kernel<<<gQKV, blk, DYN_SMEM>>>();
    cudaEventRecord(eQKV, 0);

    // side stream: P rows (needs sigma), then V transpose (needs qkv)
    cudaStreamWaitEvent(sA, eCvt, 0);
    p_row_kernel<<<N_TOK, blk, 0, sA>>>(P);
    cudaStreamWaitEvent(sA, eQKV, 0);
    transpose_v_kernel<<<dim3(D_MOD / 32, N_TOK / 32), blk, 0, sA>>>();
    cudaEventRecord(eT, sA);

    // main: E = exp((Q K^T)/sqrt(d)) + row sums   (overlaps p_row/transpose)
    dim3 gS(N_TOK / 128, N_TOK / 128);
    s_h_kernel<<<gS, blk, DYN_SMEM>>>();
    cudaEventRecord(eS, 0);

    // side stream: S output = E / rowsum  (overlaps Z GEMM)
    cudaStreamWaitEvent(sA, eS, 0);
    scale_s_kernel<<<N_TOK * 4, blk, 0, sA>>>(S);
    cudaEventRecord(eSc, sA);

    // main: Z = diag(1/rowsum) E V  (needs transpose + rowsums)
    cudaStreamWaitEvent(0, eT, 0);
    dim3 gZ(D_MOD / 128, N_TOK / 128);
    z_h_kernel<<<gZ, blk, DYN_SMEM>>>(Z);

    // join side stream back to origin before return
    cudaStreamWaitEvent(0, eSc, 0);
}

// round 11
// speedup vs baseline: 1.1684x; 1.1684x over previous
#include <cuda_runtime.h>
#include <cuda_fp16.h>
#include <math.h>
#include <stdint.h>

#define N_TOK 4096
#define D_MOD 512

// scratch (static device globals — no allocation allowed)
__device__ __half g_Xh[N_TOK * D_MOD];
__device__ __half g_Wqh[D_MOD * D_MOD];
__device__ __half g_Wkh[D_MOD * D_MOD];
__device__ __half g_Wvh[D_MOD * D_MOD];
__device__ __half g_Qh[N_TOK * D_MOD];
__device__ __half g_Kh[N_TOK * D_MOD];
__device__ __half g_Vh[N_TOK * D_MOD];
__device__ __half g_Vth[D_MOD * N_TOK];         // V^T [512][4096]
__device__ __half g_Sh[(size_t)N_TOK * N_TOK];  // exp(scores), unnormalized
__device__ float  g_rowsum[N_TOK];              // sum of exp per row

__device__ __forceinline__ uint32_t smem_u32(const void* p) {
    uint32_t a;
    asm("{ .reg .u64 t; cvta.to.shared.u64 t, %1; cvt.u32.u64 %0, t; }" : "=r"(a) : "l"(p));
    return a;
}
__device__ __forceinline__ void mma_f16(float* d, const uint32_t* a, const uint32_t* b) {
    asm volatile(
        "mma.sync.aligned.m16n8k16.row.col.f32.f16.f16.f32 "
        "{%0,%1,%2,%3}, {%4,%5,%6,%7}, {%8,%9}, {%0,%1,%2,%3};"
        : "+f"(d[0]), "+f"(d[1]), "+f"(d[2]), "+f"(d[3])
        : "r"(a[0]), "r"(a[1]), "r"(a[2]), "r"(a[3]), "r"(b[0]), "r"(b[1]));
}
__device__ __forceinline__ void ldsm4(uint32_t* r, uint32_t addr) {
    asm volatile("ldmatrix.sync.aligned.m8n8.x4.shared.b16 {%0,%1,%2,%3}, [%4];"
        : "=r"(r[0]), "=r"(r[1]), "=r"(r[2]), "=r"(r[3]) : "r"(addr));
}
__device__ __forceinline__ void cp16(uint32_t s, const void* g) {
    asm volatile("cp.async.cg.shared.global [%0], [%1], 16;" :: "r"(s), "l"(g));
}

// ---------------------------------------------------------------------------
// 128x128 tile fp16 GEMM (fp32 acc), 3-stage cp.async, ldmatrix, XOR swizzle.
//   C[M,NC] = alpha * A[M,K] * B[NC,K]^T
// MODE: 1 fp16 store | 2 exp->fp16 + rowsum atomics
// 96 KB smem -> 2 CTAs/SM.
// ---------------------------------------------------------------------------
#define STAGES 3
#define TILE_BYTES 16384
#define STAGE_BYTES (2 * TILE_BYTES)
#define DYN_SMEM (STAGES * STAGE_BYTES)       // 96 KB

template <int MODE>
__device__ __forceinline__ void gemm_fp16(
    const __half* __restrict__ A, const __half* __restrict__ B,
    void* __restrict__ Cv, int K, int NC, float alpha)
{
    extern __shared__ __half smh[];
    const uint32_t smem_base = smem_u32(smh);
    const int t    = threadIdx.x;
    const int wid  = t >> 5;
    const int lane = t & 31;
    const int r    = lane >> 2;
    const int c    = lane & 3;
    const int warpM = (wid >> 2) * 64;
    const int warpN = (wid & 3) * 32;
    const int row0 = blockIdx.y * 128;
    const int col0 = blockIdx.x * 128;
    const int iters = K >> 6;

    auto stage_load = [&](int sidx) {
        const int buf = sidx % STAGES;
        const int k0  = sidx << 6;
        const uint32_t abase = smem_base + (uint32_t)buf * STAGE_BYTES;
        const uint32_t bbase = abase + TILE_BYTES;
#pragma unroll
        for (int i = 0; i < 4; i++) {
            int lc = i * 256 + t;
            int rr = lc >> 3, cc = lc & 7;
            uint32_t so = (uint32_t)((rr << 3) + (cc ^ (rr & 7))) << 4;
            cp16(abase + so, &A[(size_t)(row0 + rr) * K + k0 + (cc << 3)]);
            cp16(bbase + so, &B[(size_t)(col0 + rr) * K + k0 + (cc << 3)]);
        }
        asm volatile("cp.async.commit_group;" ::: "memory");
    };

    const int a_row_lo = lane & 15;
    const int a_chi    = lane >> 4;
    const int b_row_lo = (lane & 7) + ((lane >> 4) << 3);
    const int b_chi    = (lane >> 3) & 1;

    float acc[4][4][4] = {};

    stage_load(0);
    stage_load(1);

    for (int it = 0; it < iters; ++it) {
        const int buf = it % STAGES;
        asm volatile("cp.async.wait_group %0;" :: "n"(STAGES - 2) : "memory");
        __syncthreads();
        if (it + STAGES - 1 < iters) stage_load(it + STAGES - 1);

        const uint32_t abase = smem_base + (uint32_t)buf * STAGE_BYTES;
        const uint32_t bbase = abase + TILE_BYTES;

#pragma unroll
        for (int kk4 = 0; kk4 < 4; kk4++) {
            const int ca = kk4 * 2 + a_chi;
            const int cb = kk4 * 2 + b_chi;
            uint32_t af[4][4], bq[2][4];
#pragma unroll
            for (int mi = 0; mi < 4; mi++) {
                int row = warpM + mi * 16 + a_row_lo;
                uint32_t addr = abase + ((uint32_t)((row << 3) + (ca ^ (row & 7))) << 4);
                ldsm4(af[mi], addr);
            }
#pragma unroll
            for (int np = 0; np < 2; np++) {
                int row = warpN + np * 16 + b_row_lo;
                uint32_t addr = bbase + ((uint32_t)((row << 3) + (cb ^ (row & 7))) << 4);
                ldsm4(bq[np], addr);
            }
#pragma unroll
            for (int mi = 0; mi < 4; mi++)
#pragma unroll
                for (int ni = 0; ni < 4; ni++)
                    mma_f16(acc[mi][ni], af[mi], &bq[ni >> 1][(ni & 1) * 2]);
        }
    }

    // ---- epilogue
#pragma unroll
    for (int mi = 0; mi < 4; mi++) {
        int row = row0 + warpM + mi * 16 + r;
        float rs0 = 0.f, rs1 = 0.f;
#pragma unroll
        for (int ni = 0; ni < 4; ni++) {
            int col = col0 + warpN + ni * 8 + 2 * c;
            float o0 = alpha * acc[mi][ni][0], o1 = alpha * acc[mi][ni][1];
            float o2 = alpha * acc[mi][ni][2], o3 = alpha * acc[mi][ni][3];
            if (MODE == 1) {
                __half* Ch = (__half*)Cv;
                *(__half2*)&Ch[(size_t)row * NC + col]       = __floats2half2_rn(o0, o1);
                *(__half2*)&Ch[(size_t)(row + 8) * NC + col] = __floats2half2_rn(o2, o3);
            } else {
                float e0 = fminf(__expf(o0), 60000.f);
                float e1 = fminf(__expf(o1), 60000.f);
                float e2 = fminf(__expf(o2), 60000.f);
                float e3 = fminf(__expf(o3), 60000.f);
                __half* Ch = (__half*)Cv;
                *(__half2*)&Ch[(size_t)row * NC + col]       = __floats2half2_rn(e0, e1);
                *(__half2*)&Ch[(size_t)(row + 8) * NC + col] = __floats2half2_rn(e2, e3);
                rs0 += e0 + e1;
                rs1 += e2 + e3;
            }
        }
        if (MODE == 2) {
            rs0 += __shfl_xor_sync(0xffffffffu, rs0, 1);
            rs0 += __shfl_xor_sync(0xffffffffu, rs0, 2);
            rs1 += __shfl_xor_sync(0xffffffffu, rs1, 1);
            rs1 += __shfl_xor_sync(0xffffffffu, rs1, 2);
            if (c == 0) {
                atomicAdd(&g_rowsum[row],     rs0);
                atomicAdd(&g_rowsum[row + 8], rs1);
            }
        }
    }
}

__global__ void __launch_bounds__(256, 2) qkv_h_kernel()
{
    if (blockIdx.z == 0)      gemm_fp16<1>(g_Xh, g_Wqh, g_Qh, D_MOD, D_MOD, 1.0f);
    else if (blockIdx.z == 1) gemm_fp16<1>(g_Xh, g_Wkh, g_Kh, D_MOD, D_MOD, 1.0f);
    else                      gemm_fp16<1>(g_Xh, g_Wvh, g_Vh, D_MOD, D_MOD, 1.0f);
}

__global__ void __launch_bounds__(256, 2) s_h_kernel()
{
    gemm_fp16<2>(g_Qh, g_Kh, g_Sh, D_MOD, N_TOK, 0.044194173824159216f); // 1/sqrt(512)
}

// ---------------------------------------------------------------------------
// Z-GEMM: BM=128, BN=64 tile (grid 8x32 = 256 CTAs; 72 KB smem -> 3 CTAs/SM).
// Z = diag(1/rowsum) * E * V   (E fp16 [4096,4096], Vt fp16 [512,4096])
// Warps 4(M) x 2(N); warp tile 32x32.
// ---------------------------------------------------------------------------
#define ZB_TILE_BYTES 8192                     // 64 rows * 128B
#define ZSTAGE_BYTES (TILE_BYTES + ZB_TILE_BYTES)   // 24 KB
#define ZDYN_SMEM (STAGES * ZSTAGE_BYTES)      // 72 KB

__global__ void __launch_bounds__(256, 3) z_h_kernel(float* __restrict__ Z)
{
    extern __shared__ __half smh[];
    const uint32_t smem_base = smem_u32(smh);
    const int t    = threadIdx.x;
    const int wid  = t >> 5;
    const int lane = t & 31;
    const int r    = lane >> 2;
    const int c    = lane & 3;
    const int warpM = (wid >> 1) * 32;    // 4 warps in M
    const int warpN = (wid & 1) * 32;     // 2 warps in N
    const int row0 = blockIdx.y * 128;
    const int col0 = blockIdx.x * 64;
    const int K = N_TOK, NC = D_MOD;
    const int iters = K >> 6;              // 64

    const __half* A = g_Sh;
    const __half* B = g_Vth;

    auto stage_load = [&](int sidx) {
        const int buf = sidx % STAGES;
        const int k0  = sidx << 6;
        const uint32_t abase = smem_base + (uint32_t)buf * ZSTAGE_BYTES;
        const uint32_t bbase = abase + TILE_BYTES;
#pragma unroll
        for (int i = 0; i < 4; i++) {       // A: 1024 chunks
            int lc = i * 256 + t;
            int rr = lc >> 3, cc = lc & 7;
            uint32_t so = (uint32_t)((rr << 3) + (cc ^ (rr & 7))) << 4;
            cp16(abase + so, &A[(size_t)(row0 + rr) * K + k0 + (cc << 3)]);
        }
#pragma unroll
        for (int i = 0; i < 2; i++) {       // B: 512 chunks
            int lc = i * 256 + t;
            int rr = lc >> 3, cc = lc & 7;
            uint32_t so = (uint32_t)((rr << 3) + (cc ^ (rr & 7))) << 4;
            cp16(bbase + so, &B[(size_t)(col0 + rr) * K + k0 + (cc << 3)]);
        }
        asm volatile("cp.async.commit_group;" ::: "memory");
    };

    const int a_row_lo = lane & 15;
    const int a_chi    = lane >> 4;
    const int b_row_lo = (lane & 7) + ((lane >> 4) << 3);
    const int b_chi    = (lane >> 3) & 1;

    float acc[2][4][4] = {};

    stage_load(0);
    stage_load(1);

    for (int it = 0; it < iters; ++it) {
        const int buf = it % STAGES;
        asm volatile("cp.async.wait_group %0;" :: "n"(STAGES - 2) : "memory");
        __syncthreads();
        if (it + STAGES - 1 < iters) stage_load(it + STAGES - 1);

        const uint32_t abase = smem_base + (uint32_t)buf * ZSTAGE_BYTES;
        const uint32_t bbase = abase + TILE_BYTES;

#pragma unroll
        for (int kk4 = 0; kk4 < 4; kk4++) {
            const int ca = kk4 * 2 + a_chi;
            const int cb = kk4 * 2 + b_chi;
            uint32_t af[2][4], bq[2][4];
#pragma unroll
            for (int mi = 0; mi < 2; mi++) {
                int row = warpM + mi * 16 + a_row_lo;
                uint32_t addr = abase + ((uint32_t)((row << 3) + (ca ^ (row & 7))) << 4);
                ldsm4(af[mi], addr);
            }
#pragma unroll
            for (int np = 0; np < 2; np++) {
                int row = warpN + np * 16 + b_row_lo;
                uint32_t addr = bbase + ((uint32_t)((row << 3) + (cb ^ (row & 7))) << 4);
                ldsm4(bq[np], addr);
            }
#pragma unroll
            for (int mi = 0; mi < 2; mi++)
#pragma unroll
                for (int ni = 0; ni < 4; ni++)
                    mma_f16(acc[mi][ni], af[mi], &bq[ni >> 1][(ni & 1) * 2]);
        }
    }

#pragma unroll
    for (int mi = 0; mi < 2; mi++) {
        int row = row0 + warpM + mi * 16 + r;
        float inv0 = 1.0f / g_rowsum[row];
        float inv1 = 1.0f / g_rowsum[row + 8];
#pragma unroll
        for (int ni = 0; ni < 4; ni++) {
            int col = col0 + warpN + ni * 8 + 2 * c;
            *(float2*)&Z[(size_t)row * NC + col] =
                make_float2(acc[mi][ni][0] * inv0, acc[mi][ni][1] * inv0);
            *(float2*)&Z[(size_t)(row + 8) * NC + col] =
                make_float2(acc[mi][ni][2] * inv1, acc[mi][ni][3] * inv1);
        }
    }
}

// ---------------------------------------------------------------------------
// fused fp32 -> fp16 convert for x, Wq, Wk, Wv
// ---------------------------------------------------------------------------
#define X4   (N_TOK * D_MOD / 4)
#define W4   (D_MOD * D_MOD / 4)

__global__ void cvt_all_kernel(const float4* __restrict__ x,
                               const float4* __restrict__ Wq,
                               const float4* __restrict__ Wk,
                               const float4* __restrict__ Wv)
{
    int i = blockIdx.x * blockDim.x + threadIdx.x;
    const float4* in;
    __half* out;
    int idx;
    if (i < X4)                { in = x;  out = g_Xh;  idx = i; }
    else if (i < X4 + W4)      { in = Wq; out = g_Wqh; idx = i - X4; }
    else if (i < X4 + 2 * W4)  { in = Wk; out = g_Wkh; idx = i - X4 - W4; }
    else if (i < X4 + 3 * W4)  { in = Wv; out = g_Wvh; idx = i - X4 - 2 * W4; }
    else return;
    float4 v = in[idx];
    *(__half2*)&out[idx * 4]     = __floats2half2_rn(v.x, v.y);
    *(__half2*)&out[idx * 4 + 2] = __floats2half2_rn(v.z, v.w);
}

// ---------------------------------------------------------------------------
// transpose g_Vh [4096][512] -> g_Vth [512][4096]
// ---------------------------------------------------------------------------
__global__ void transpose_v_kernel()
{
    __shared__ __half tile[32][33];
    const int c0 = blockIdx.x * 32;
    const int r0 = blockIdx.y * 32;
    const int tx = threadIdx.x & 31;
    const int ty = threadIdx.x >> 5;
#pragma unroll
    for (int i = 0; i < 4; i++) {
        int row = ty + i * 8;
        tile[row][tx] = g_Vh[(size_t)(r0 + row) * D_MOD + c0 + tx];
    }
    __syncthreads();
#pragma unroll
    for (int i = 0; i < 4; i++) {
        int row = ty + i * 8;
        g_Vth[(size_t)(c0 + row) * N_TOK + r0 + tx] = tile[tx][row];
    }
}

// ---------------------------------------------------------------------------
// P row kernel: per-row sigma (x.Ws, clipped), zero row, Gaussian band.
// fp32 underflow: exp term is exactly 0 for |i-j| >= 15 since sigma <= 1.
// ---------------------------------------------------------------------------
#define BAND 32

__global__ void p_row_kernel(float* __restrict__ P,
                             const float* __restrict__ x,
                             const float* __restrict__ Ws)
{
    __shared__ float red[8];
    const int row = blockIdx.x;
    const int t = threadIdx.x;
    const int lane = t & 31, w = t >> 5;

    // sigma = clip(x[row,:].Ws)
    float s;
    {
        float2 a = *(const float2*)&x[(size_t)row * D_MOD + t * 2];
        float2 b = *(const float2*)&Ws[t * 2];
        s = a.x * b.x + a.y * b.y;
#pragma unroll
        for (int o = 16; o; o >>= 1) s += __shfl_xor_sync(0xffffffffu, s, o);
        if (lane == 0) red[w] = s;
    }

    // zero the row while reduction settles
    float4* prow4 = (float4*)(P + (size_t)row * N_TOK);
#pragma unroll
    for (int j = t; j < N_TOK / 4; j += 256)
        prow4[j] = make_float4(0.f, 0.f, 0.f, 0.f);
    __syncthreads();

    if (t < 32) {
        float sg = red[0];
#pragma unroll
        for (int i = 1; i < 8; i++) sg += red[i];
        sg = fminf(fmaxf(sg, 0.001f), 1.0f);
        const float inv = 1.0f / sg;
        const float cc  = rsqrtf(6.283185307179586f * sg);
        const int j0 = max(row - BAND, 0);
        const int j1 = min(row + BAND, N_TOK - 1);

        float sum = 0.f;
        for (int j = j0 + lane; j <= j1; j += 32) {
            float u = (float)(j - row) * inv;
            sum += cc * __expf(-0.5f * u * u);
        }
#pragma unroll
        for (int o = 16; o; o >>= 1) sum += __shfl_xor_sync(0xffffffffu, sum, o);
        const float scale = 1.0f / (sum + 1e-8f);

        for (int j = j0 + lane; j <= j1; j += 32) {
            float u = (float)(j - row) * inv;
            P[(size_t)row * N_TOK + j] = cc * __expf(-0.5f * u * u) * scale;
        }
    }
}

// ---------------------------------------------------------------------------
// scale S: S_fp32 = e_fp16 * (1/rowsum). 4 blocks per row, 4 floats/thread.
// ---------------------------------------------------------------------------
__global__ void scale_s_kernel(float* __restrict__ S)
{
    __shared__ float sh_inv;
    const int b = blockIdx.x;
    const int row = b >> 2;
    if (threadIdx.x == 0) sh_inv = 1.0f / g_rowsum[row];
    __syncthreads();
    const float inv = sh_inv;
    const size_t base = (size_t)b * 1024 + threadIdx.x * 4;
    __half2 h01 = *(const __half2*)&g_Sh[base];
    __half2 h23 = *(const __half2*)&g_Sh[base + 2];
    float2 f01 = __half22float2(h01);
    float2 f23 = __half22float2(h23);
    float4 o;
    o.x = f01.x * inv; o.y = f01.y * inv;
    o.z = f23.x * inv; o.w = f23.y * inv;
    *(float4*)&S[base] = o;
}

// ---------------------------------------------------------------------------
extern "C" void kernel_launch(void* const* d_in, const int* in_sizes, int n_in,
                              void* d_out, int out_size)
{
    const float* x  = (const float*)d_in[0];
    const float* Wq = (const float*)d_in[1];
    const float* Wk = (const float*)d_in[2];
    const float* Wv = (const float*)d_in[3];
    const float* Ws = (const float*)d_in[4];

    float* out = (float*)d_out;
    float* Z = out;                          // [4096, 512]
    float* P = out + (size_t)N_TOK * D_MOD;  // [4096, 4096]
    float* S = P + (size_t)N_TOK * N_TOK;    // [4096, 4096]

    cudaFuncSetAttribute(qkv_h_kernel, cudaFuncAttributeMaxDynamicSharedMemorySize, DYN_SMEM);
    cudaFuncSetAttribute(s_h_kernel,   cudaFuncAttributeMaxDynamicSharedMemorySize, DYN_SMEM);
    cudaFuncSetAttribute(z_h_kernel,   cudaFuncAttributeMaxDynamicSharedMemorySize, ZDYN_SMEM);

    float* rsp;
    cudaGetSymbolAddress((void**)&rsp, g_rowsum);

    dim3 blk(256);

    // 0) zero rowsum accumulator
    cudaMemsetAsync(rsp, 0, N_TOK * sizeof(float));

    // 1) convert inputs to fp16 (one launch)
    cvt_all_kernel<<<(X4 + 3 * W4) / 256, blk>>>(
        (const float4*)x, (const float4*)Wq, (const float4*)Wk, (const float4*)Wv);

    // 2) Q, K, V = x @ W^T  (fp16 outputs)
    dim3 gQKV(D_MOD / 128, N_TOK / 128, 3);
    qkv_h_kernel<<<gQKV, blk, DYN_SMEM>>>();

    // 2b) Vt
    transpose_v_kernel<<<dim3(D_MOD / 32, N_TOK / 32), blk>>>();

    // 3) P rows (sigma computed in-kernel)
    p_row_kernel<<<N_TOK, blk>>>(P, x, Ws);

    // 4) E = exp((Q K^T)/sqrt(d)) -> g_Sh (fp16) + row sums
    dim3 gS(N_TOK / 128, N_TOK / 128);
    s_h_kernel<<<gS, blk, DYN_SMEM>>>();

    // 5) S output = E / rowsum
    scale_s_kernel<<<N_TOK * 4, blk>>>(S);

    // 6) Z = diag(1/rowsum) E V  (BN=64 tile, 256 CTAs, 3 CTA/SM)
    dim3 gZ(D_MOD / 64, N_TOK / 128);
    z_h_kernel<<<gZ, blk, ZDYN_SMEM>>>(Z);
}

// round 12
// speedup vs baseline: 1.1697x; 1.0012x over previous
#include <cuda_runtime.h>
#include <cuda_fp16.h>
#include <math.h>
#include <stdint.h>

#define N_TOK 4096
#define D_MOD 512

// scratch (static device globals — no allocation allowed)
__device__ __half g_Xh[N_TOK * D_MOD];
__device__ __half g_Wqh[D_MOD * D_MOD];
__device__ __half g_Wkh[D_MOD * D_MOD];
__device__ __half g_Wvh[D_MOD * D_MOD];
__device__ __half g_Qh[N_TOK * D_MOD];
__device__ __half g_Kh[N_TOK * D_MOD];
__device__ __half g_Vth[D_MOD * N_TOK];         // V^T [512][4096]
__device__ __half g_Sh[(size_t)N_TOK * N_TOK];  // exp(scores), unnormalized
__device__ float  g_rowsum[N_TOK];              // sum of exp per row

__device__ __forceinline__ uint32_t smem_u32(const void* p) {
    uint32_t a;
    asm("{ .reg .u64 t; cvta.to.shared.u64 t, %1; cvt.u32.u64 %0, t; }" : "=r"(a) : "l"(p));
    return a;
}
__device__ __forceinline__ void mma_f16(float* d, const uint32_t* a, const uint32_t* b) {
    asm volatile(
        "mma.sync.aligned.m16n8k16.row.col.f32.f16.f16.f32 "
        "{%0,%1,%2,%3}, {%4,%5,%6,%7}, {%8,%9}, {%0,%1,%2,%3};"
        : "+f"(d[0]), "+f"(d[1]), "+f"(d[2]), "+f"(d[3])
        : "r"(a[0]), "r"(a[1]), "r"(a[2]), "r"(a[3]), "r"(b[0]), "r"(b[1]));
}
__device__ __forceinline__ void ldsm4(uint32_t* r, uint32_t addr) {
    asm volatile("ldmatrix.sync.aligned.m8n8.x4.shared.b16 {%0,%1,%2,%3}, [%4];"
        : "=r"(r[0]), "=r"(r[1]), "=r"(r[2]), "=r"(r[3]) : "r"(addr));
}
__device__ __forceinline__ void cp16(uint32_t s, const void* g) {
    asm volatile("cp.async.cg.shared.global [%0], [%1], 16;" :: "r"(s), "l"(g));
}

// ---------------------------------------------------------------------------
// 128x128 tile fp16 GEMM (fp32 acc), 3-stage cp.async, ldmatrix, XOR swizzle.
//   C[M,NC] = alpha * A[M,K] * B[NC,K]^T
// MODE: 1 fp16 store | 2 exp->fp16 + rowsum atomics | 4 fp16 TRANSPOSED store
// 96 KB smem -> 2 CTAs/SM.
// ---------------------------------------------------------------------------
#define STAGES 3
#define TILE_BYTES 16384
#define STAGE_BYTES (2 * TILE_BYTES)
#define DYN_SMEM (STAGES * STAGE_BYTES)       // 96 KB
#define TLD 136                               // transpose stage row stride (halves)

template <int MODE>
__device__ __forceinline__ void gemm_fp16(
    const __half* __restrict__ A, const __half* __restrict__ B,
    void* __restrict__ Cv, int K, int NC, float alpha)
{
    extern __shared__ __half smh[];
    const uint32_t smem_base = smem_u32(smh);
    const int t    = threadIdx.x;
    const int wid  = t >> 5;
    const int lane = t & 31;
    const int r    = lane >> 2;
    const int c    = lane & 3;
    const int warpM = (wid >> 2) * 64;
    const int warpN = (wid & 3) * 32;
    const int row0 = blockIdx.y * 128;
    const int col0 = blockIdx.x * 128;
    const int iters = K >> 6;

    auto stage_load = [&](int sidx) {
        const int buf = sidx % STAGES;
        const int k0  = sidx << 6;
        const uint32_t abase = smem_base + (uint32_t)buf * STAGE_BYTES;
        const uint32_t bbase = abase + TILE_BYTES;
#pragma unroll
        for (int i = 0; i < 4; i++) {
            int lc = i * 256 + t;
            int rr = lc >> 3, cc = lc & 7;
            uint32_t so = (uint32_t)((rr << 3) + (cc ^ (rr & 7))) << 4;
            cp16(abase + so, &A[(size_t)(row0 + rr) * K + k0 + (cc << 3)]);
            cp16(bbase + so, &B[(size_t)(col0 + rr) * K + k0 + (cc << 3)]);
        }
        asm volatile("cp.async.commit_group;" ::: "memory");
    };

    const int a_row_lo = lane & 15;
    const int a_chi    = lane >> 4;
    const int b_row_lo = (lane & 7) + ((lane >> 4) << 3);
    const int b_chi    = (lane >> 3) & 1;

    float acc[4][4][4] = {};

    stage_load(0);
    stage_load(1);

    for (int it = 0; it < iters; ++it) {
        const int buf = it % STAGES;
        asm volatile("cp.async.wait_group %0;" :: "n"(STAGES - 2) : "memory");
        __syncthreads();
        if (it + STAGES - 1 < iters) stage_load(it + STAGES - 1);

        const uint32_t abase = smem_base + (uint32_t)buf * STAGE_BYTES;
        const uint32_t bbase = abase + TILE_BYTES;

#pragma unroll
        for (int kk4 = 0; kk4 < 4; kk4++) {
            const int ca = kk4 * 2 + a_chi;
            const int cb = kk4 * 2 + b_chi;
            uint32_t af[4][4], bq[2][4];
#pragma unroll
            for (int mi = 0; mi < 4; mi++) {
                int row = warpM + mi * 16 + a_row_lo;
                uint32_t addr = abase + ((uint32_t)((row << 3) + (ca ^ (row & 7))) << 4);
                ldsm4(af[mi], addr);
            }
#pragma unroll
            for (int np = 0; np < 2; np++) {
                int row = warpN + np * 16 + b_row_lo;
                uint32_t addr = bbase + ((uint32_t)((row << 3) + (cb ^ (row & 7))) << 4);
                ldsm4(bq[np], addr);
            }
#pragma unroll
            for (int mi = 0; mi < 4; mi++)
#pragma unroll
                for (int ni = 0; ni < 4; ni++)
                    mma_f16(acc[mi][ni], af[mi], &bq[ni >> 1][(ni & 1) * 2]);
        }
    }

    // ---- epilogue
    if (MODE == 4) {
        // stage transposed fp16 tile in smem, then coalesced store to Vt
        __syncthreads();                     // all warps done reading stages
#pragma unroll
        for (int mi = 0; mi < 4; mi++) {
            int rl0 = warpM + mi * 16 + r;
            int rl1 = rl0 + 8;
#pragma unroll
            for (int ni = 0; ni < 4; ni++) {
                int cl = warpN + ni * 8 + 2 * c;
                smh[(cl + 0) * TLD + rl0] = __float2half_rn(acc[mi][ni][0]);
                smh[(cl + 1) * TLD + rl0] = __float2half_rn(acc[mi][ni][1]);
                smh[(cl + 0) * TLD + rl1] = __float2half_rn(acc[mi][ni][2]);
                smh[(cl + 1) * TLD + rl1] = __float2half_rn(acc[mi][ni][3]);
            }
        }
        __syncthreads();
        __half* Vt = (__half*)Cv;
#pragma unroll
        for (int i = 0; i < 4; i++) {
            int l = i * 256 + t;
            int rr = l >> 3;                 // Vt-local row (V column)
            int cc = (l & 7) * 16;           // halves within row
            uint4 v0 = *(uint4*)&smh[rr * TLD + cc];
            uint4 v1 = *(uint4*)&smh[rr * TLD + cc + 8];
            *(uint4*)&Vt[(size_t)(col0 + rr) * N_TOK + row0 + cc]     = v0;
            *(uint4*)&Vt[(size_t)(col0 + rr) * N_TOK + row0 + cc + 8] = v1;
        }
        return;
    }

#pragma unroll
    for (int mi = 0; mi < 4; mi++) {
        int row = row0 + warpM + mi * 16 + r;
        float rs0 = 0.f, rs1 = 0.f;
#pragma unroll
        for (int ni = 0; ni < 4; ni++) {
            int col = col0 + warpN + ni * 8 + 2 * c;
            float o0 = alpha * acc[mi][ni][0], o1 = alpha * acc[mi][ni][1];
            float o2 = alpha * acc[mi][ni][2], o3 = alpha * acc[mi][ni][3];
            if (MODE == 1) {
                __half* Ch = (__half*)Cv;
                *(__half2*)&Ch[(size_t)row * NC + col]       = __floats2half2_rn(o0, o1);
                *(__half2*)&Ch[(size_t)(row + 8) * NC + col] = __floats2half2_rn(o2, o3);
            } else {
                float e0 = fminf(__expf(o0), 60000.f);
                float e1 = fminf(__expf(o1), 60000.f);
                float e2 = fminf(__expf(o2), 60000.f);
                float e3 = fminf(__expf(o3), 60000.f);
                __half* Ch = (__half*)Cv;
                *(__half2*)&Ch[(size_t)row * NC + col]       = __floats2half2_rn(e0, e1);
                *(__half2*)&Ch[(size_t)(row + 8) * NC + col] = __floats2half2_rn(e2, e3);
                rs0 += e0 + e1;
                rs1 += e2 + e3;
            }
        }
        if (MODE == 2) {
            rs0 += __shfl_xor_sync(0xffffffffu, rs0, 1);
            rs0 += __shfl_xor_sync(0xffffffffu, rs0, 2);
            rs1 += __shfl_xor_sync(0xffffffffu, rs1, 1);
            rs1 += __shfl_xor_sync(0xffffffffu, rs1, 2);
            if (c == 0) {
                atomicAdd(&g_rowsum[row],     rs0);
                atomicAdd(&g_rowsum[row + 8], rs1);
            }
        }
    }
}

__global__ void __launch_bounds__(256, 2) qkv_h_kernel()
{
    if (blockIdx.z == 0)      gemm_fp16<1>(g_Xh, g_Wqh, g_Qh, D_MOD, D_MOD, 1.0f);
    else if (blockIdx.z == 1) gemm_fp16<1>(g_Xh, g_Wkh, g_Kh, D_MOD, D_MOD, 1.0f);
    else                      gemm_fp16<4>(g_Xh, g_Wvh, g_Vth, D_MOD, D_MOD, 1.0f);
}

__global__ void __launch_bounds__(256, 2) s_h_kernel()
{
    gemm_fp16<2>(g_Qh, g_Kh, g_Sh, D_MOD, N_TOK, 0.044194173824159216f); // 1/sqrt(512)
}

// ---------------------------------------------------------------------------
// Z-GEMM: BM=128, BN=64 tile (grid 8x32 = 256 CTAs; 72 KB smem -> 3 CTAs/SM).
// Z = diag(1/rowsum) * E * V
// ---------------------------------------------------------------------------
#define ZB_TILE_BYTES 8192
#define ZSTAGE_BYTES (TILE_BYTES + ZB_TILE_BYTES)
#define ZDYN_SMEM (STAGES * ZSTAGE_BYTES)      // 72 KB

__global__ void __launch_bounds__(256, 3) z_h_kernel(float* __restrict__ Z)
{
    extern __shared__ __half smh[];
    const uint32_t smem_base = smem_u32(smh);
    const int t    = threadIdx.x;
    const int wid  = t >> 5;
    const int lane = t & 31;
    const int r    = lane >> 2;
    const int c    = lane & 3;
    const int warpM = (wid >> 1) * 32;
    const int warpN = (wid & 1) * 32;
    const int row0 = blockIdx.y * 128;
    const int col0 = blockIdx.x * 64;
    const int K = N_TOK, NC = D_MOD;
    const int iters = K >> 6;

    const __half* A = g_Sh;
    const __half* B = g_Vth;

    auto stage_load = [&](int sidx) {
        const int buf = sidx % STAGES;
        const int k0  = sidx << 6;
        const uint32_t abase = smem_base + (uint32_t)buf * ZSTAGE_BYTES;
        const uint32_t bbase = abase + TILE_BYTES;
#pragma unroll
        for (int i = 0; i < 4; i++) {
            int lc = i * 256 + t;
            int rr = lc >> 3, cc = lc & 7;
            uint32_t so = (uint32_t)((rr << 3) + (cc ^ (rr & 7))) << 4;
            cp16(abase + so, &A[(size_t)(row0 + rr) * K + k0 + (cc << 3)]);
        }
#pragma unroll
        for (int i = 0; i < 2; i++) {
            int lc = i * 256 + t;
            int rr = lc >> 3, cc = lc & 7;
            uint32_t so = (uint32_t)((rr << 3) + (cc ^ (rr & 7))) << 4;
            cp16(bbase + so, &B[(size_t)(col0 + rr) * K + k0 + (cc << 3)]);
        }
        asm volatile("cp.async.commit_group;" ::: "memory");
    };

    const int a_row_lo = lane & 15;
    const int a_chi    = lane >> 4;
    const int b_row_lo = (lane & 7) + ((lane >> 4) << 3);
    const int b_chi    = (lane >> 3) & 1;

    float acc[2][4][4] = {};

    stage_load(0);
    stage_load(1);

    for (int it = 0; it < iters; ++it) {
        const int buf = it % STAGES;
        asm volatile("cp.async.wait_group %0;" :: "n"(STAGES - 2) : "memory");
        __syncthreads();
        if (it + STAGES - 1 < iters) stage_load(it + STAGES - 1);

        const uint32_t abase = smem_base + (uint32_t)buf * ZSTAGE_BYTES;
        const uint32_t bbase = abase + TILE_BYTES;

#pragma unroll
        for (int kk4 = 0; kk4 < 4; kk4++) {
            const int ca = kk4 * 2 + a_chi;
            const int cb = kk4 * 2 + b_chi;
            uint32_t af[2][4], bq[2][4];
#pragma unroll
            for (int mi = 0; mi < 2; mi++) {
                int row = warpM + mi * 16 + a_row_lo;
                uint32_t addr = abase + ((uint32_t)((row << 3) + (ca ^ (row & 7))) << 4);
                ldsm4(af[mi], addr);
            }
#pragma unroll
            for (int np = 0; np < 2; np++) {
                int row = warpN + np * 16 + b_row_lo;
                uint32_t addr = bbase + ((uint32_t)((row << 3) + (cb ^ (row & 7))) << 4);
                ldsm4(bq[np], addr);
            }
#pragma unroll
            for (int mi = 0; mi < 2; mi++)
#pragma unroll
                for (int ni = 0; ni < 4; ni++)
                    mma_f16(acc[mi][ni], af[mi], &bq[ni >> 1][(ni & 1) * 2]);
        }
    }

#pragma unroll
    for (int mi = 0; mi < 2; mi++) {
        int row = row0 + warpM + mi * 16 + r;
        float inv0 = 1.0f / g_rowsum[row];
        float inv1 = 1.0f / g_rowsum[row + 8];
#pragma unroll
        for (int ni = 0; ni < 4; ni++) {
            int col = col0 + warpN + ni * 8 + 2 * c;
            *(float2*)&Z[(size_t)row * NC + col] =
                make_float2(acc[mi][ni][0] * inv0, acc[mi][ni][1] * inv0);
            *(float2*)&Z[(size_t)(row + 8) * NC + col] =
                make_float2(acc[mi][ni][2] * inv1, acc[mi][ni][3] * inv1);
        }
    }
}

// ---------------------------------------------------------------------------
// fused fp32 -> fp16 convert for x, Wq, Wk, Wv
// ---------------------------------------------------------------------------
#define X4   (N_TOK * D_MOD / 4)
#define W4   (D_MOD * D_MOD / 4)

__global__ void cvt_all_kernel(const float4* __restrict__ x,
                               const float4* __restrict__ Wq,
                               const float4* __restrict__ Wk,
                               const float4* __restrict__ Wv)
{
    int i = blockIdx.x * blockDim.x + threadIdx.x;
    const float4* in;
    __half* out;
    int idx;
    if (i < X4)                { in = x;  out = g_Xh;  idx = i; }
    else if (i < X4 + W4)      { in = Wq; out = g_Wqh; idx = i - X4; }
    else if (i < X4 + 2 * W4)  { in = Wk; out = g_Wkh; idx = i - X4 - W4; }
    else if (i < X4 + 3 * W4)  { in = Wv; out = g_Wvh; idx = i - X4 - 2 * W4; }
    else return;
    float4 v = in[idx];
    *(__half2*)&out[idx * 4]     = __floats2half2_rn(v.x, v.y);
    *(__half2*)&out[idx * 4 + 2] = __floats2half2_rn(v.z, v.w);
}

// ---------------------------------------------------------------------------
// P band kernel: P already zeroed by memset. One warp per row: sigma + band.
// fp32 underflow: exp term is exactly 0 for |i-j| >= 15 since sigma <= 1.
// ---------------------------------------------------------------------------
#define BAND 32

__global__ void p_band_kernel(float* __restrict__ P,
                              const float* __restrict__ x,
                              const float* __restrict__ Ws)
{
    const int row  = blockIdx.x * 8 + (threadIdx.x >> 5);
    const int lane = threadIdx.x & 31;

    // sigma = clip(x[row,:].Ws)
    const float4* xr = (const float4*)(x + (size_t)row * D_MOD);
    const float4* w  = (const float4*)Ws;
    float s = 0.f;
#pragma unroll
    for (int k = lane; k < D_MOD / 4; k += 32) {
        float4 a = xr[k], b = w[k];
        s += a.x * b.x + a.y * b.y + a.z * b.z + a.w * b.w;
    }
#pragma unroll
    for (int o = 16; o; o >>= 1) s += __shfl_xor_sync(0xffffffffu, s, o);
    const float sg  = fminf(fmaxf(s, 0.001f), 1.0f);
    const float inv = 1.0f / sg;
    const float cc  = rsqrtf(6.283185307179586f * sg);
    const int j0 = max(row - BAND, 0);
    const int j1 = min(row + BAND, N_TOK - 1);

    float sum = 0.f;
    for (int j = j0 + lane; j <= j1; j += 32) {
        float u = (float)(j - row) * inv;
        sum += cc * __expf(-0.5f * u * u);
    }
#pragma unroll
    for (int o = 16; o; o >>= 1) sum += __shfl_xor_sync(0xffffffffu, sum, o);
    const float scale = 1.0f / (sum + 1e-8f);

    for (int j = j0 + lane; j <= j1; j += 32) {
        float u = (float)(j - row) * inv;
        P[(size_t)row * N_TOK + j] = cc * __expf(-0.5f * u * u) * scale;
    }
}

// ---------------------------------------------------------------------------
// scale S: S_fp32 = e_fp16 * (1/rowsum). 4 blocks per row, 4 floats/thread.
// ---------------------------------------------------------------------------
__global__ void scale_s_kernel(float* __restrict__ S)
{
    __shared__ float sh_inv;
    const int b = blockIdx.x;
    const int row = b >> 2;
    if (threadIdx.x == 0) sh_inv = 1.0f / g_rowsum[row];
    __syncthreads();
    const float inv = sh_inv;
    const size_t base = (size_t)b * 1024 + threadIdx.x * 4;
    __half2 h01 = *(const __half2*)&g_Sh[base];
    __half2 h23 = *(const __half2*)&g_Sh[base + 2];
    float2 f01 = __half22float2(h01);
    float2 f23 = __half22float2(h23);
    float4 o;
    o.x = f01.x * inv; o.y = f01.y * inv;
    o.z = f23.x * inv; o.w = f23.y * inv;
    *(float4*)&S[base] = o;
}

// ---------------------------------------------------------------------------
extern "C" void kernel_launch(void* const* d_in, const int* in_sizes, int n_in,
                              void* d_out, int out_size)
{
    const float* x  = (const float*)d_in[0];
    const float* Wq = (const float*)d_in[1];
    const float* Wk = (const float*)d_in[2];
    const float* Wv = (const float*)d_in[3];
    const float* Ws = (const float*)d_in[4];

    float* out = (float*)d_out;
    float* Z = out;                          // [4096, 512]
    float* P = out + (size_t)N_TOK * D_MOD;  // [4096, 4096]
    float* S = P + (size_t)N_TOK * N_TOK;    // [4096, 4096]

    cudaFuncSetAttribute(qkv_h_kernel, cudaFuncAttributeMaxDynamicSharedMemorySize, DYN_SMEM);
    cudaFuncSetAttribute(s_h_kernel,   cudaFuncAttributeMaxDynamicSharedMemorySize, DYN_SMEM);
    cudaFuncSetAttribute(z_h_kernel,   cudaFuncAttributeMaxDynamicSharedMemorySize, ZDYN_SMEM);

    float* rsp;
    cudaGetSymbolAddress((void**)&rsp, g_rowsum);

    dim3 blk(256);

    // 0) zero rowsum accumulator and all of P (driver memset path)
    cudaMemsetAsync(rsp, 0, N_TOK * sizeof(float));
    cudaMemsetAsync(P, 0, (size_t)N_TOK * N_TOK * sizeof(float));

    // 1) convert inputs to fp16 (one launch)
    cvt_all_kernel<<<(X4 + 3 * W4) / 256, blk>>>(
        (const float4*)x, (const float4*)Wq, (const float4*)Wk, (const float4*)Wv);

    // 2) Q, K = x @ W^T (fp16); Vt = (x @ Wv^T)^T via MODE-4 epilogue
    dim3 gQKV(D_MOD / 128, N_TOK / 128, 3);
    qkv_h_kernel<<<gQKV, blk, DYN_SMEM>>>();

    // 3) P Gaussian band (P already zeroed)
    p_band_kernel<<<N_TOK / 8, blk>>>(P, x, Ws);

    // 4) E = exp((Q K^T)/sqrt(d)) -> g_Sh (fp16) + row sums
    dim3 gS(N_TOK / 128, N_TOK / 128);
    s_h_kernel<<<gS, blk, DYN_SMEM>>>();

    // 5) S output = E / rowsum
    scale_s_kernel<<<N_TOK * 4, blk>>>(S);

    // 6) Z = diag(1/rowsum) E V
    dim3 gZ(D_MOD / 64, N_TOK / 128);
    z_h_kernel<<<gZ, blk, ZDYN_SMEM>>>(Z);
}